// round 16
// baseline (speedup 1.0000x reference)
#include <cuda_runtime.h>
#include <cuda_fp16.h>
#include <cstdint>

// Shapes (fixed)
#define S_LEN 2048
#define D_MODEL 4096
#define N_HEADS 32
#define N_KV 8
#define HD 128

// Scratch (allocation-free rule: device globals)
__device__ uint32_t g_qh[S_LEN * N_HEADS * 64];         // fp16 Q (rope'd, scaled)
__device__ uint32_t g_attn[S_LEN * N_HEADS * HD / 2];   // fp16 packed tiles
__device__ uint32_t g_xp[S_LEN * D_MODEL / 2];          // fp16 packed x
__device__ uint32_t g_wqkv[48 * 64 * 4096];             // packed [wq|wk|wv]
__device__ uint32_t g_woT[4096 * 4096 / 2];
__device__ uint32_t g_kh[8 * 32 * 4096];                // K fp16 tiles
__device__ uint32_t g_vt[8 * 32 * 4096];                // V^T fp16 tiles

// GEMM packed tile: [rowblk(128)][chunk(64 k)][128 x 32 half2], swizzled
#define SWZ(r, c2) (((r) << 5) + ((c2) ^ (((r) & 7) << 2)))
#define TILE_U32 4096
#define TILE_B 16384
// Attention K tile: [64 r][64 half2]; V^T tile: [128 d][32 half2]
#define KSWZ(r, c2) (((r) << 6) + ((c2) ^ (((r) & 7) << 2)))
#define VSWZ(r, c2) (((r) << 5) + ((c2) ^ (((r) & 7) << 2)))

#define QK_SCALE 0.08838834764831845f
#define NPERSIST 296

// ---------------------------------------------------------------------------
// Helpers (baseline PTX only)
// ---------------------------------------------------------------------------
__device__ __forceinline__ uint32_t smem_u32(const void* p) {
    uint32_t a;
    asm("{ .reg .u64 t; cvta.to.shared.u64 t, %1; cvt.u32.u64 %0, t; }" : "=r"(a) : "l"(p));
    return a;
}
#define MBARRIER_INIT(mbar, cnt) \
    asm volatile("mbarrier.init.shared.b64 [%0], %1;" :: "r"((uint32_t)(mbar)), "r"((uint32_t)(cnt)) : "memory")
#define MBARRIER_EXPECT_TX(mbar, bytes) \
    asm volatile("mbarrier.arrive.expect_tx.shared.b64 _, [%0], %1;" :: "r"((uint32_t)(mbar)), "r"((uint32_t)(bytes)) : "memory")
#define MBARRIER_WAIT_PARITY(mbar, par) do {                                        \
    uint32_t _m = (uint32_t)(mbar); uint32_t _p = (uint32_t)(par); uint32_t _d;     \
    asm volatile("{\n\t.reg .pred p;\n\t"                                           \
        "mbarrier.try_wait.parity.acquire.cta.shared::cta.b64 p, [%1], %2;\n\t"     \
        "selp.b32 %0, 1, 0, p;\n\t}" : "=r"(_d) : "r"(_m), "r"(_p) : "memory");     \
    if (!_d) {                                                                      \
        asm volatile("{\n\t.reg .pred P1;\n\t"                                      \
            "WL_%=:\n\t"                                                            \
            "mbarrier.try_wait.parity.acquire.cta.shared::cta.b64 P1, [%0], %1, 0x989680;\n\t" \
            "@P1 bra.uni WD_%=;\n\t"                                                \
            "bra.uni WL_%=;\n\t"                                                    \
            "WD_%=:\n\t}" :: "r"(_m), "r"(_p) : "memory");                          \
    }                                                                               \
} while (0)

__device__ __forceinline__ void bulk_g2s(uint32_t dst, const void* src,
                                         uint32_t bytes, uint32_t mbar) {
    asm volatile(
        "cp.async.bulk.shared::cluster.global.mbarrier::complete_tx::bytes [%0], [%1], %2, [%3];"
        :: "r"(dst), "l"(src), "r"(bytes), "r"(mbar) : "memory");
}

__device__ __forceinline__ void mma16816(float* d, const uint32_t* a, const uint32_t* b) {
    asm volatile(
        "mma.sync.aligned.m16n8k16.row.col.f32.f16.f16.f32 "
        "{%0,%1,%2,%3}, {%4,%5,%6,%7}, {%8,%9}, {%0,%1,%2,%3};"
        : "+f"(d[0]), "+f"(d[1]), "+f"(d[2]), "+f"(d[3])
        : "r"(a[0]), "r"(a[1]), "r"(a[2]), "r"(a[3]), "r"(b[0]), "r"(b[1]));
}

#define LDSM4(r0, r1, r2, r3, addr) \
    asm volatile("ldmatrix.sync.aligned.m8n8.x4.shared.b16 {%0,%1,%2,%3}, [%4];" \
                 : "=r"(r0), "=r"(r1), "=r"(r2), "=r"(r3) : "r"(addr))

// ---------------------------------------------------------------------------
// Persistent fp16 mma.sync GEMM, ldmatrix-fed.
// mode 0: plain fp32 C store. mode 1: QKV fused epilogue.
// ---------------------------------------------------------------------------
#define STAGE_B (2 * TILE_B)
#define NSTG 3
#define GEMM_SMEM (1024 + NSTG * STAGE_B)

__global__ __launch_bounds__(256, 2)
void mma_gemm(const uint32_t* __restrict__ Ap, const uint32_t* __restrict__ Bp,
              float* __restrict__ C, int M, int N, int K, int mode,
              const float* __restrict__ fc, const float* __restrict__ fs,
              uint32_t* __restrict__ Qo, uint32_t* __restrict__ Kh,
              uint32_t* __restrict__ Vt) {
    extern __shared__ char smem[];
    const uint32_t sb = smem_u32(smem);
    const int tid = threadIdx.x;
    const int wid = tid >> 5, lane = tid & 31;
    const int wm = wid & 3;
    const int wn = wid >> 2;
    const int mlane = lane >> 2;
    const int klane = lane & 3;
    const int lq = lane >> 3, lr = lane & 7;
    const int nch = K >> 6;

    if (tid == 0) {
#pragma unroll
        for (int s = 0; s < NSTG; s++) MBARRIER_INIT(sb + 8 * s, 1);
    }
    __syncthreads();

    const int ar0 = wm * 32 + (lq & 1) * 8 + lr;
    const int ac4 = (lq >> 1) * 4;
    const int br_ = wn * 64 + (lq >> 1) * 8 + lr;
    const int bc4 = (lq & 1) * 4;

    const int ntx = N >> 7;
    const int ntiles = ntx * (M >> 7);
    int fph = 0;                           // persists across tiles

    for (int tile = blockIdx.x; tile < ntiles; tile += gridDim.x) {
        const int bx = tile % ntx;
        const int by = tile / ntx;
        const uint32_t* Abase = Ap + (size_t)by * nch * TILE_U32;
        const uint32_t* Bbase = Bp + (size_t)bx * nch * TILE_U32;

        auto issue = [&](int chunk, int st) {
            uint32_t base = sb + 1024 + st * STAGE_B;
            MBARRIER_EXPECT_TX(sb + 8 * st, STAGE_B);
            bulk_g2s(base, Abase + (size_t)chunk * TILE_U32, TILE_B, sb + 8 * st);
            bulk_g2s(base + TILE_B, Bbase + (size_t)chunk * TILE_U32, TILE_B, sb + 8 * st);
        };

        __syncthreads();   // prior tile's reads + V-epilogue smem staging done
        if (tid == 0) { issue(0, 0); issue(1, 1); }

        float acc[2][8][4];
#pragma unroll
        for (int mi = 0; mi < 2; mi++)
#pragma unroll
            for (int ni = 0; ni < 8; ni++)
#pragma unroll
                for (int j = 0; j < 4; j++) acc[mi][ni][j] = 0.f;

        int st = 0;
        int pk = 2, pst = 2;

        for (int it = 0; it < nch; it++) {
            __syncthreads();
            if (pk < nch) {
                if (tid == 0) issue(pk, pst);
                pk++; pst++; if (pst == NSTG) pst = 0;
            }
            MBARRIER_WAIT_PARITY(sb + 8 * st, (fph >> st) & 1);
            fph ^= 1 << st;

            const uint32_t Aadr = sb + 1024 + st * STAGE_B;
            const uint32_t Badr = Aadr + TILE_B;

#pragma unroll
            for (int s = 0; s < 4; s++) {
                const int c2b = s * 8;
                uint32_t a[2][4];
                LDSM4(a[0][0], a[0][1], a[0][2], a[0][3],
                      Aadr + 4 * SWZ(ar0, c2b + ac4));
                LDSM4(a[1][0], a[1][1], a[1][2], a[1][3],
                      Aadr + 4 * SWZ(ar0 + 16, c2b + ac4));
#pragma unroll
                for (int j = 0; j < 4; j++) {
                    uint32_t b0, b1, b2, b3;
                    LDSM4(b0, b1, b2, b3, Badr + 4 * SWZ(br_ + j * 16, c2b + bc4));
                    uint32_t blo[2] = { b0, b1 }, bhi[2] = { b2, b3 };
                    mma16816(acc[0][2 * j],     a[0], blo);
                    mma16816(acc[0][2 * j + 1], a[0], bhi);
                    mma16816(acc[1][2 * j],     a[1], blo);
                    mma16816(acc[1][2 * j + 1], a[1], bhi);
                }
            }

            st++; if (st == NSTG) st = 0;
        }

        const int row0 = by * 128;
        const int col0 = bx * 128;

        if (mode == 0) {
#pragma unroll
            for (int mi = 0; mi < 2; mi++) {
                int row = row0 + wm * 32 + mi * 16 + mlane;
#pragma unroll
                for (int ni = 0; ni < 8; ni++) {
                    int col = col0 + wn * 64 + ni * 8 + 2 * klane;
                    *(float2*)&C[(size_t)row * N + col] =
                        make_float2(acc[mi][ni][0], acc[mi][ni][1]);
                    *(float2*)&C[(size_t)(row + 8) * N + col] =
                        make_float2(acc[mi][ni][2], acc[mi][ni][3]);
                }
            }
            continue;
        }

        // QKV epilogue. Region uniform per tile (col0 multiple of 128).
        if (col0 < 4096) {
            // Q: rope + scale + fp16, out [s][h][64 half2]
#pragma unroll
            for (int mi = 0; mi < 2; mi++) {
                int s0 = row0 + wm * 32 + mi * 16 + mlane;
#pragma unroll
                for (int ni = 0; ni < 8; ni++) {
                    int c = col0 + wn * 64 + ni * 8 + 2 * klane;
                    int h = c >> 7, i2 = (c & 127) >> 1;
#pragma unroll
                    for (int g = 0; g < 2; g++) {
                        int s = s0 + g * 8;
                        float cs = fc[s * 64 + i2], sn = fs[s * 64 + i2];
                        float av = acc[mi][ni][2 * g], bv = acc[mi][ni][2 * g + 1];
                        __half2 hv = __floats2half2_rn((av * cs - bv * sn) * QK_SCALE,
                                                       (av * sn + bv * cs) * QK_SCALE);
                        Qo[((size_t)s * N_HEADS + h) * 64 + i2] = *(uint32_t*)&hv;
                    }
                }
            }
        } else if (col0 < 5120) {
            // K: rope + fp16 round into attention tiles
#pragma unroll
            for (int mi = 0; mi < 2; mi++) {
                int s0 = row0 + wm * 32 + mi * 16 + mlane;
#pragma unroll
                for (int ni = 0; ni < 8; ni++) {
                    int kc = col0 - 4096 + wn * 64 + ni * 8 + 2 * klane;
                    int kv = kc >> 7, i2 = (kc & 127) >> 1;
#pragma unroll
                    for (int g = 0; g < 2; g++) {
                        int s = s0 + g * 8;
                        float cs = fc[s * 64 + i2], sn = fs[s * 64 + i2];
                        float av = acc[mi][ni][2 * g], bv = acc[mi][ni][2 * g + 1];
                        __half2 hv = __floats2half2_rn(av * cs - bv * sn,
                                                       av * sn + bv * cs);
                        int t = kv * 32 + (s >> 6), r = s & 63;
                        Kh[(size_t)t * 4096 + KSWZ(r, i2)] = *(uint32_t*)&hv;
                    }
                }
            }
        } else {
            // V: stage fp16 in smem, then emit V^T tiles directly.
            uint32_t* stp = (uint32_t*)(smem + 1024);   // aliases stage buffers
            __syncthreads();
#pragma unroll
            for (int mi = 0; mi < 2; mi++) {
                int sl0 = wm * 32 + mi * 16 + mlane;
#pragma unroll
                for (int ni = 0; ni < 8; ni++) {
                    int d = wn * 64 + ni * 8 + 2 * klane;
#pragma unroll
                    for (int g = 0; g < 2; g++) {
                        __half2 v = __floats2half2_rn(acc[mi][ni][2 * g],
                                                      acc[mi][ni][2 * g + 1]);
                        stp[(sl0 + g * 8) * 65 + (d >> 1)] = *(uint32_t*)&v;
                    }
                }
            }
            __syncthreads();
            const int kv = bx - 40;
            const int tile0 = kv * 32 + (row0 >> 6);
            for (int i = tid; i < 8192; i += 256) {
                int d = i & 127;
                int jj = (i >> 7) & 31;
                int ch = i >> 12;
                int sl = ch * 64 + 2 * jj;
                uint32_t u0 = stp[sl * 65 + (d >> 1)];
                uint32_t u1 = stp[(sl + 1) * 65 + (d >> 1)];
                __half h0 = (d & 1) ? ((__half2*)&u0)->y : ((__half2*)&u0)->x;
                __half h1 = (d & 1) ? ((__half2*)&u1)->y : ((__half2*)&u1)->x;
                __half2 out = __halves2half2(h0, h1);
                Vt[(size_t)(tile0 + ch) * 4096 + VSWZ(d, jj)] = *(uint32_t*)&out;
            }
        }
    }
}

// ---------------------------------------------------------------------------
// Merged prep: z=0 wq, z=1 wk, z=2 wv, z=3 wo (transpose+fp16+pack),
// z=4: pack x (no transpose).
// ---------------------------------------------------------------------------
__global__ void pack_w_all(const float* __restrict__ wq, const float* __restrict__ wk,
                           const float* __restrict__ wv, const float* __restrict__ wo,
                           const float* __restrict__ x,
                           uint32_t* __restrict__ wqkv, uint32_t* __restrict__ woT,
                           uint32_t* __restrict__ xp) {
    const int z = blockIdx.z;
    int tx = threadIdx.x, ty = threadIdx.y;

    if (z == 4) {
        int bidl = blockIdx.y * 128 + blockIdx.x;
        if (bidl >= 8192) return;
        int idx = bidl * 256 + ty * 32 + tx;
        int s = idx >> 10;
        int d4 = (idx & 1023) << 2;
        float4 v = *(const float4*)&x[(size_t)s * D_MODEL + d4];
        int rowblk = s >> 7, r = s & 127;
        int chunk = d4 >> 6;
        int c2 = (d4 & 63) >> 1;
        __half2 lo = __floats2half2_rn(v.x, v.y);
        __half2 hi = __floats2half2_rn(v.z, v.w);
        uint32_t* dst = &xp[((size_t)rowblk * 64 + chunk) * TILE_U32 + SWZ(r, c2)];
        *(uint2*)dst = make_uint2(*(uint32_t*)&lo, *(uint32_t*)&hi);
        return;
    }

    const float* W; uint32_t* P; int C; int colblk0;
    if (z == 0)      { W = wq; P = wqkv; C = 4096; colblk0 = 0; }
    else if (z == 1) { W = wk; P = wqkv; C = 1024; colblk0 = 32; }
    else if (z == 2) { W = wv; P = wqkv; C = 1024; colblk0 = 40; }
    else             { W = wo; P = woT;  C = 4096; colblk0 = 0; }
    int bx = blockIdx.x * 32;
    if (bx >= C) return;
    int by = blockIdx.y * 32;

    __shared__ float t[32][33];
#pragma unroll
    for (int i = 0; i < 32; i += 8)
        t[ty + i][tx] = W[(size_t)(by + ty + i) * C + bx + tx];
    __syncthreads();
    const int kk2 = tx & 15;
    const int kglob = by + 2 * kk2;
    const int chunk = kglob >> 6;
    const int c2 = (kglob & 63) >> 1;
    const int nbase = (tx >> 4) * 8 + ty;
#pragma unroll
    for (int g = 0; g < 2; g++) {
        int nloc = nbase + g * 16;
        int n = bx + nloc;
        int colblk = colblk0 + (n >> 7), r = n & 127;
        __half2 v = __floats2half2_rn(t[2 * kk2][nloc], t[2 * kk2 + 1][nloc]);
        P[((size_t)colblk * 64 + chunk) * TILE_U32 + SWZ(r, c2)] = *(uint32_t*)&v;
    }
}

// ---------------------------------------------------------------------------
// Tensor-core flash attention (causal), ldmatrix-fed, LPT-ordered.
// 1 CTA = 64 queries x 1 head (4 warps, 2 CTAs/SM). 3-stage pipeline.
// Lazy-rescale softmax (fixed reference M, warp-uniform skip).
// ---------------------------------------------------------------------------
#define FA_STAGE 32768
#define FA_NSTG 3
#define FA_SMEM (1024 + FA_NSTG * FA_STAGE)

__global__ __launch_bounds__(128, 2)
void fa_kernel(const uint32_t* __restrict__ Q, const uint32_t* __restrict__ Kp,
               const uint32_t* __restrict__ Vp, uint32_t* __restrict__ O) {
    extern __shared__ char smem[];
    const uint32_t sb = smem_u32(smem);
    const int tid = threadIdx.x;
    const int w = tid >> 5, lane = tid & 31;
    const int lq = lane >> 3, lr = lane & 7;
    const int h = blockIdx.y;
    const int kvh = h >> 2;
    const int qblk = gridDim.x - 1 - blockIdx.x;    // LPT: longest CTAs first
    const int q0 = qblk * 64;

    if (tid == 0) {
#pragma unroll
        for (int s = 0; s < FA_NSTG; s++) MBARRIER_INIT(sb + 8 * s, 1);
    }
    __syncthreads();

    const int rq = q0 + w * 16 + (lane >> 2);
    const uint32_t* q0p = Q + ((size_t)rq * N_HEADS + h) * 64;
    const uint32_t* q1p = Q + ((size_t)(rq + 8) * N_HEADS + h) * 64;
    uint32_t qf[8][4];
#pragma unroll
    for (int kk = 0; kk < 8; kk++) {
        int cb = kk * 8 + (lane & 3);
        qf[kk][0] = q0p[cb];
        qf[kk][1] = q1p[cb];
        qf[kk][2] = q0p[cb + 4];
        qf[kk][3] = q1p[cb + 4];
    }

    const int nc = qblk + 1;
    const uint32_t* Kt = Kp + (size_t)(kvh * 32) * 4096;
    const uint32_t* Vt = Vp + (size_t)(kvh * 32) * 4096;

    auto issue = [&](int c, int st) {
        uint32_t base = sb + 1024 + st * FA_STAGE;
        MBARRIER_EXPECT_TX(sb + 8 * st, FA_STAGE);
        bulk_g2s(base, Kt + (size_t)c * 4096, 16384, sb + 8 * st);
        bulk_g2s(base + 16384, Vt + (size_t)c * 4096, 16384, sb + 8 * st);
    };
    if (tid == 0) {
        issue(0, 0);
        if (nc > 1) issue(1, 1);
        if (nc > 2) issue(2, 2);
    }

    float M0 = -1e30f, M1 = -1e30f, lp0 = 0.f, lp1 = 0.f;
    float oacc[16][4];
#pragma unroll
    for (int i = 0; i < 16; i++)
#pragma unroll
        for (int j = 0; j < 4; j++) oacc[i][j] = 0.f;

    int fph = 0;
    int st = 0;
    const int sbrow = (lq >> 1) * 8 + lr;
    const int sbc4 = (lq & 1) * 4;

    for (int c = 0; c < nc; c++) {
        MBARRIER_WAIT_PARITY(sb + 8 * st, (fph >> st) & 1);
        fph ^= 1 << st;

        const uint32_t KhA = sb + 1024 + st * FA_STAGE;
        const uint32_t VsA = KhA + 16384;

        float sacc[8][4];
#pragma unroll
        for (int nt = 0; nt < 8; nt++)
#pragma unroll
            for (int j = 0; j < 4; j++) sacc[nt][j] = 0.f;

#pragma unroll
        for (int kk = 0; kk < 8; kk++) {
            const int c2b = kk * 8 + sbc4;
#pragma unroll
            for (int j = 0; j < 4; j++) {
                uint32_t adr = 4 * KSWZ(sbrow + j * 16, c2b);
                uint32_t h0, h1, h2, h3;
                LDSM4(h0, h1, h2, h3, KhA + adr);
                uint32_t bh0[2] = { h0, h1 }, bh1[2] = { h2, h3 };
                mma16816(sacc[2 * j],     qf[kk], bh0);
                mma16816(sacc[2 * j + 1], qf[kk], bh1);
            }
        }

        if (c == qblk) {
#pragma unroll
            for (int nt = 0; nt < 8; nt++) {
                int cg = c * 64 + nt * 8 + 2 * (lane & 3);
                if (cg > rq)          sacc[nt][0] = -1e30f;
                if (cg + 1 > rq)      sacc[nt][1] = -1e30f;
                if (cg > rq + 8)      sacc[nt][2] = -1e30f;
                if (cg + 1 > rq + 8)  sacc[nt][3] = -1e30f;
            }
        }

        float mx0 = -1e30f, mx1 = -1e30f;
#pragma unroll
        for (int nt = 0; nt < 8; nt++) {
            mx0 = fmaxf(mx0, fmaxf(sacc[nt][0], sacc[nt][1]));
            mx1 = fmaxf(mx1, fmaxf(sacc[nt][2], sacc[nt][3]));
        }
        bool trig = (mx0 > M0 + 6.9f) || (mx1 > M1 + 6.9f);
        if (__any_sync(0xffffffff, trig)) {
            float r0 = fmaxf(mx0, __shfl_xor_sync(0xffffffff, mx0, 1));
            r0 = fmaxf(r0, __shfl_xor_sync(0xffffffff, r0, 2));
            float r1 = fmaxf(mx1, __shfl_xor_sync(0xffffffff, mx1, 1));
            r1 = fmaxf(r1, __shfl_xor_sync(0xffffffff, r1, 2));
            float Mn0 = fmaxf(M0, r0), Mn1 = fmaxf(M1, r1);
            float c0 = __expf(M0 - Mn0), c1 = __expf(M1 - Mn1);
            lp0 *= c0; lp1 *= c1;
#pragma unroll
            for (int i = 0; i < 16; i++) {
                oacc[i][0] *= c0; oacc[i][1] *= c0;
                oacc[i][2] *= c1; oacc[i][3] *= c1;
            }
            M0 = Mn0; M1 = Mn1;
        }

        uint32_t pf[4][4];
#pragma unroll
        for (int nt = 0; nt < 8; nt++) {
            float p0 = __expf(sacc[nt][0] - M0);
            float p1 = __expf(sacc[nt][1] - M0);
            float p2 = __expf(sacc[nt][2] - M1);
            float p3 = __expf(sacc[nt][3] - M1);
            lp0 += p0 + p1; lp1 += p2 + p3;
            __half2 h01 = __floats2half2_rn(p0, p1);
            __half2 h23 = __floats2half2_rn(p2, p3);
            int kt = nt >> 1, hi = (nt & 1) << 1;
            pf[kt][hi]     = *(uint32_t*)&h01;
            pf[kt][hi + 1] = *(uint32_t*)&h23;
        }

#pragma unroll
        for (int jj = 0; jj < 8; jj++) {
#pragma unroll
            for (int kt = 0; kt < 4; kt++) {
                uint32_t b0, b1, b2, b3;
                LDSM4(b0, b1, b2, b3,
                      VsA + 4 * VSWZ(sbrow + jj * 16, kt * 8 + sbc4));
                uint32_t blo[2] = { b0, b1 }, bhi[2] = { b2, b3 };
                mma16816(oacc[2 * jj],     pf[kt], blo);
                mma16816(oacc[2 * jj + 1], pf[kt], bhi);
            }
        }

        __syncthreads();
        if (tid == 0 && c + 3 < nc) issue(c + 3, st);

        st++; if (st == FA_NSTG) st = 0;
    }

    float l0 = lp0, l1 = lp1;
    l0 += __shfl_xor_sync(0xffffffff, l0, 1);
    l0 += __shfl_xor_sync(0xffffffff, l0, 2);
    l1 += __shfl_xor_sync(0xffffffff, l1, 1);
    l1 += __shfl_xor_sync(0xffffffff, l1, 2);

    float i0 = 1.f / l0, i1 = 1.f / l1;
    const int s0r = rq, s1r = rq + 8;
    const int rb0 = s0r >> 7, ri0 = s0r & 127;
    const int rb1 = s1r >> 7, ri1 = s1r & 127;
#pragma unroll
    for (int nt2 = 0; nt2 < 16; nt2++) {
        int d = nt2 * 8 + 2 * (lane & 3);
        int gdim = h * HD + d;
        int chunk = gdim >> 6;
        int c2 = (gdim & 63) >> 1;
        __half2 vlo = __floats2half2_rn(oacc[nt2][0] * i0, oacc[nt2][1] * i0);
        __half2 vhi = __floats2half2_rn(oacc[nt2][2] * i1, oacc[nt2][3] * i1);
        O[((size_t)rb0 * 64 + chunk) * TILE_U32 + SWZ(ri0, c2)] = *(uint32_t*)&vlo;
        O[((size_t)rb1 * 64 + chunk) * TILE_U32 + SWZ(ri1, c2)] = *(uint32_t*)&vhi;
    }
}

// ---------------------------------------------------------------------------
// Host launcher
// ---------------------------------------------------------------------------
extern "C" void kernel_launch(void* const* d_in, const int* in_sizes, int n_in,
                              void* d_out, int out_size) {
    const float* x  = (const float*)d_in[0];
    const float* fc = (const float*)d_in[1];
    const float* fs = (const float*)d_in[2];
    const float* wq = (const float*)d_in[4];
    const float* wk = (const float*)d_in[5];
    const float* wv = (const float*)d_in[6];
    const float* wo = (const float*)d_in[7];
    float* out = (float*)d_out;

    uint32_t *qp, *ap, *xp, *wqkv, *woT, *kh, *vt;
    cudaGetSymbolAddress((void**)&qp, g_qh);
    cudaGetSymbolAddress((void**)&ap, g_attn);
    cudaGetSymbolAddress((void**)&xp, g_xp);
    cudaGetSymbolAddress((void**)&wqkv, g_wqkv);
    cudaGetSymbolAddress((void**)&woT, g_woT);
    cudaGetSymbolAddress((void**)&kh, g_kh);
    cudaGetSymbolAddress((void**)&vt, g_vt);

    cudaFuncSetAttribute(mma_gemm, cudaFuncAttributeMaxDynamicSharedMemorySize, GEMM_SMEM);
    cudaFuncSetAttribute(fa_kernel, cudaFuncAttributeMaxDynamicSharedMemorySize, FA_SMEM);

    // 1: all weight packs + x pack in one launch
    pack_w_all<<<dim3(128, 128, 5), dim3(32, 8)>>>(wq, wk, wv, wo, x, wqkv, woT, xp);

    // 2: fused QKV projection (persistent grid)
    mma_gemm<<<NPERSIST, 256, GEMM_SMEM>>>(
        xp, wqkv, nullptr, S_LEN, 6144, 4096, 1, fc, fs, qp, kh, vt);

    // 3: flash attention (tensor cores, 64-query CTAs, LPT order, 3-stage)
    fa_kernel<<<dim3(S_LEN / 64, N_HEADS), 128, FA_SMEM>>>(qp, kh, vt, ap);

    // 4: output projection (persistent grid)
    mma_gemm<<<NPERSIST, 256, GEMM_SMEM>>>(
        ap, woT, out, S_LEN, 4096, 4096, 0, nullptr, nullptr, nullptr, nullptr, nullptr);
}

// round 17
// speedup vs baseline: 1.0239x; 1.0239x over previous
#include <cuda_runtime.h>
#include <cuda_fp16.h>
#include <cstdint>

// Shapes (fixed)
#define S_LEN 2048
#define D_MODEL 4096
#define N_HEADS 32
#define N_KV 8
#define HD 128

// Scratch (allocation-free rule: device globals)
__device__ uint32_t g_qh[S_LEN * N_HEADS * 64];         // fp16 Q (rope'd, scaled)
__device__ uint32_t g_attn[S_LEN * N_HEADS * HD / 2];   // fp16 packed tiles
__device__ uint32_t g_xp[S_LEN * D_MODEL / 2];          // fp16 packed x
__device__ uint32_t g_wqkv[48 * 64 * 4096];             // packed [wq|wk|wv]
__device__ uint32_t g_woT[4096 * 4096 / 2];
__device__ uint32_t g_kh[8 * 32 * 4096];                // K fp16 tiles
__device__ uint32_t g_vt[8 * 32 * 4096];                // V^T fp16 tiles

// GEMM packed tile: [rowblk(128)][chunk(64 k)][128 x 32 half2], swizzled
#define SWZ(r, c2) (((r) << 5) + ((c2) ^ (((r) & 7) << 2)))
#define TILE_U32 4096
#define TILE_B 16384
// Attention K tile: [64 r][64 half2]; V^T tile: [128 d][32 half2]
#define KSWZ(r, c2) (((r) << 6) + ((c2) ^ (((r) & 7) << 2)))
#define VSWZ(r, c2) (((r) << 5) + ((c2) ^ (((r) & 7) << 2)))

#define QK_SCALE 0.08838834764831845f

// ---------------------------------------------------------------------------
// Helpers (baseline PTX only)
// ---------------------------------------------------------------------------
__device__ __forceinline__ uint32_t smem_u32(const void* p) {
    uint32_t a;
    asm("{ .reg .u64 t; cvta.to.shared.u64 t, %1; cvt.u32.u64 %0, t; }" : "=r"(a) : "l"(p));
    return a;
}
#define MBARRIER_INIT(mbar, cnt) \
    asm volatile("mbarrier.init.shared.b64 [%0], %1;" :: "r"((uint32_t)(mbar)), "r"((uint32_t)(cnt)) : "memory")
#define MBARRIER_EXPECT_TX(mbar, bytes) \
    asm volatile("mbarrier.arrive.expect_tx.shared.b64 _, [%0], %1;" :: "r"((uint32_t)(mbar)), "r"((uint32_t)(bytes)) : "memory")
#define MBARRIER_WAIT_PARITY(mbar, par) do {                                        \
    uint32_t _m = (uint32_t)(mbar); uint32_t _p = (uint32_t)(par); uint32_t _d;     \
    asm volatile("{\n\t.reg .pred p;\n\t"                                           \
        "mbarrier.try_wait.parity.acquire.cta.shared::cta.b64 p, [%1], %2;\n\t"     \
        "selp.b32 %0, 1, 0, p;\n\t}" : "=r"(_d) : "r"(_m), "r"(_p) : "memory");     \
    if (!_d) {                                                                      \
        asm volatile("{\n\t.reg .pred P1;\n\t"                                      \
            "WL_%=:\n\t"                                                            \
            "mbarrier.try_wait.parity.acquire.cta.shared::cta.b64 P1, [%0], %1, 0x989680;\n\t" \
            "@P1 bra.uni WD_%=;\n\t"                                                \
            "bra.uni WL_%=;\n\t"                                                    \
            "WD_%=:\n\t}" :: "r"(_m), "r"(_p) : "memory");                          \
    }                                                                               \
} while (0)

__device__ __forceinline__ void bulk_g2s(uint32_t dst, const void* src,
                                         uint32_t bytes, uint32_t mbar) {
    asm volatile(
        "cp.async.bulk.shared::cluster.global.mbarrier::complete_tx::bytes [%0], [%1], %2, [%3];"
        :: "r"(dst), "l"(src), "r"(bytes), "r"(mbar) : "memory");
}

__device__ __forceinline__ void mma16816(float* d, const uint32_t* a, const uint32_t* b) {
    asm volatile(
        "mma.sync.aligned.m16n8k16.row.col.f32.f16.f16.f32 "
        "{%0,%1,%2,%3}, {%4,%5,%6,%7}, {%8,%9}, {%0,%1,%2,%3};"
        : "+f"(d[0]), "+f"(d[1]), "+f"(d[2]), "+f"(d[3])
        : "r"(a[0]), "r"(a[1]), "r"(a[2]), "r"(a[3]), "r"(b[0]), "r"(b[1]));
}

#define LDSM4(r0, r1, r2, r3, addr) \
    asm volatile("ldmatrix.sync.aligned.m8n8.x4.shared.b16 {%0,%1,%2,%3}, [%4];" \
                 : "=r"(r0), "=r"(r1), "=r"(r2), "=r"(r3) : "r"(addr))

// ---------------------------------------------------------------------------
// fp16 mma.sync GEMM, ldmatrix-fed (grid-per-tile, proven).
// mode 0: plain fp32 C store. mode 1: QKV fused epilogue.
// ---------------------------------------------------------------------------
#define STAGE_B (2 * TILE_B)
#define NSTG 3
#define GEMM_SMEM (1024 + NSTG * STAGE_B)

__global__ __launch_bounds__(256, 2)
void mma_gemm(const uint32_t* __restrict__ Ap, const uint32_t* __restrict__ Bp,
              float* __restrict__ C, int M, int N, int K, int mode,
              const float* __restrict__ fc, const float* __restrict__ fs,
              uint32_t* __restrict__ Qo, uint32_t* __restrict__ Kh,
              uint32_t* __restrict__ Vt) {
    extern __shared__ char smem[];
    const uint32_t sb = smem_u32(smem);
    const int tid = threadIdx.x;
    const int wid = tid >> 5, lane = tid & 31;
    const int wm = wid & 3;
    const int wn = wid >> 2;
    const int mlane = lane >> 2;
    const int klane = lane & 3;
    const int lq = lane >> 3, lr = lane & 7;
    const int nch = K >> 6;

    if (tid == 0) {
#pragma unroll
        for (int s = 0; s < NSTG; s++) MBARRIER_INIT(sb + 8 * s, 1);
    }
    __syncthreads();

    const uint32_t* Abase = Ap + (size_t)blockIdx.y * nch * TILE_U32;
    const uint32_t* Bbase = Bp + (size_t)blockIdx.x * nch * TILE_U32;

    auto issue = [&](int chunk, int st) {
        uint32_t base = sb + 1024 + st * STAGE_B;
        MBARRIER_EXPECT_TX(sb + 8 * st, STAGE_B);
        bulk_g2s(base, Abase + (size_t)chunk * TILE_U32, TILE_B, sb + 8 * st);
        bulk_g2s(base + TILE_B, Bbase + (size_t)chunk * TILE_U32, TILE_B, sb + 8 * st);
    };

    if (tid == 0) { issue(0, 0); issue(1, 1); }

    float acc[2][8][4];
#pragma unroll
    for (int mi = 0; mi < 2; mi++)
#pragma unroll
        for (int ni = 0; ni < 8; ni++)
#pragma unroll
            for (int j = 0; j < 4; j++) acc[mi][ni][j] = 0.f;

    const int ar0 = wm * 32 + (lq & 1) * 8 + lr;
    const int ac4 = (lq >> 1) * 4;
    const int br_ = wn * 64 + (lq >> 1) * 8 + lr;
    const int bc4 = (lq & 1) * 4;

    int fph = 0;
    int st = 0;
    int pk = 2, pst = 2;

    for (int it = 0; it < nch; it++) {
        __syncthreads();
        if (pk < nch) {
            if (tid == 0) issue(pk, pst);
            pk++; pst++; if (pst == NSTG) pst = 0;
        }
        MBARRIER_WAIT_PARITY(sb + 8 * st, (fph >> st) & 1);
        fph ^= 1 << st;

        const uint32_t Aadr = sb + 1024 + st * STAGE_B;
        const uint32_t Badr = Aadr + TILE_B;

#pragma unroll
        for (int s = 0; s < 4; s++) {
            const int c2b = s * 8;
            uint32_t a[2][4];
            LDSM4(a[0][0], a[0][1], a[0][2], a[0][3],
                  Aadr + 4 * SWZ(ar0, c2b + ac4));
            LDSM4(a[1][0], a[1][1], a[1][2], a[1][3],
                  Aadr + 4 * SWZ(ar0 + 16, c2b + ac4));
#pragma unroll
            for (int j = 0; j < 4; j++) {
                uint32_t b0, b1, b2, b3;
                LDSM4(b0, b1, b2, b3, Badr + 4 * SWZ(br_ + j * 16, c2b + bc4));
                uint32_t blo[2] = { b0, b1 }, bhi[2] = { b2, b3 };
                mma16816(acc[0][2 * j],     a[0], blo);
                mma16816(acc[0][2 * j + 1], a[0], bhi);
                mma16816(acc[1][2 * j],     a[1], blo);
                mma16816(acc[1][2 * j + 1], a[1], bhi);
            }
        }

        st++; if (st == NSTG) st = 0;
    }

    const int row0 = blockIdx.y * 128;
    const int col0 = blockIdx.x * 128;

    if (mode == 0) {
#pragma unroll
        for (int mi = 0; mi < 2; mi++) {
            int row = row0 + wm * 32 + mi * 16 + mlane;
#pragma unroll
            for (int ni = 0; ni < 8; ni++) {
                int col = col0 + wn * 64 + ni * 8 + 2 * klane;
                *(float2*)&C[(size_t)row * N + col] =
                    make_float2(acc[mi][ni][0], acc[mi][ni][1]);
                *(float2*)&C[(size_t)(row + 8) * N + col] =
                    make_float2(acc[mi][ni][2], acc[mi][ni][3]);
            }
        }
        return;
    }

    // QKV epilogue. Region uniform per CTA (col0 multiple of 128).
    if (col0 < 4096) {
        // Q: rope + scale + fp16, out [s][h][64 half2]
#pragma unroll
        for (int mi = 0; mi < 2; mi++) {
            int s0 = row0 + wm * 32 + mi * 16 + mlane;
#pragma unroll
            for (int ni = 0; ni < 8; ni++) {
                int c = col0 + wn * 64 + ni * 8 + 2 * klane;
                int h = c >> 7, i2 = (c & 127) >> 1;
#pragma unroll
                for (int g = 0; g < 2; g++) {
                    int s = s0 + g * 8;
                    float cs = fc[s * 64 + i2], sn = fs[s * 64 + i2];
                    float av = acc[mi][ni][2 * g], bv = acc[mi][ni][2 * g + 1];
                    __half2 hv = __floats2half2_rn((av * cs - bv * sn) * QK_SCALE,
                                                   (av * sn + bv * cs) * QK_SCALE);
                    Qo[((size_t)s * N_HEADS + h) * 64 + i2] = *(uint32_t*)&hv;
                }
            }
        }
    } else if (col0 < 5120) {
        // K: rope + fp16 round into attention tiles
#pragma unroll
        for (int mi = 0; mi < 2; mi++) {
            int s0 = row0 + wm * 32 + mi * 16 + mlane;
#pragma unroll
            for (int ni = 0; ni < 8; ni++) {
                int kc = col0 - 4096 + wn * 64 + ni * 8 + 2 * klane;
                int kv = kc >> 7, i2 = (kc & 127) >> 1;
#pragma unroll
                for (int g = 0; g < 2; g++) {
                    int s = s0 + g * 8;
                    float cs = fc[s * 64 + i2], sn = fs[s * 64 + i2];
                    float av = acc[mi][ni][2 * g], bv = acc[mi][ni][2 * g + 1];
                    __half2 hv = __floats2half2_rn(av * cs - bv * sn,
                                                   av * sn + bv * cs);
                    int t = kv * 32 + (s >> 6), r = s & 63;
                    Kh[(size_t)t * 4096 + KSWZ(r, i2)] = *(uint32_t*)&hv;
                }
            }
        }
    } else {
        // V: stage fp16 in smem, then emit V^T tiles directly.
        uint32_t* stp = (uint32_t*)(smem + 1024);
        __syncthreads();
#pragma unroll
        for (int mi = 0; mi < 2; mi++) {
            int sl0 = wm * 32 + mi * 16 + mlane;
#pragma unroll
            for (int ni = 0; ni < 8; ni++) {
                int d = wn * 64 + ni * 8 + 2 * klane;
#pragma unroll
                for (int g = 0; g < 2; g++) {
                    __half2 v = __floats2half2_rn(acc[mi][ni][2 * g],
                                                  acc[mi][ni][2 * g + 1]);
                    stp[(sl0 + g * 8) * 65 + (d >> 1)] = *(uint32_t*)&v;
                }
            }
        }
        __syncthreads();
        const int kv = blockIdx.x - 40;
        const int tile0 = kv * 32 + (row0 >> 6);
        for (int i = tid; i < 8192; i += 256) {
            int d = i & 127;
            int jj = (i >> 7) & 31;
            int ch = i >> 12;
            int sl = ch * 64 + 2 * jj;
            uint32_t u0 = stp[sl * 65 + (d >> 1)];
            uint32_t u1 = stp[(sl + 1) * 65 + (d >> 1)];
            __half h0 = (d & 1) ? ((__half2*)&u0)->y : ((__half2*)&u0)->x;
            __half h1 = (d & 1) ? ((__half2*)&u1)->y : ((__half2*)&u1)->x;
            __half2 out = __halves2half2(h0, h1);
            Vt[(size_t)(tile0 + ch) * 4096 + VSWZ(d, jj)] = *(uint32_t*)&out;
        }
    }
}

// ---------------------------------------------------------------------------
// Merged prep: z=0 wq, z=1 wk, z=2 wv, z=3 wo (transpose+fp16+pack),
// z=4: pack x (no transpose).
// ---------------------------------------------------------------------------
__global__ void pack_w_all(const float* __restrict__ wq, const float* __restrict__ wk,
                           const float* __restrict__ wv, const float* __restrict__ wo,
                           const float* __restrict__ x,
                           uint32_t* __restrict__ wqkv, uint32_t* __restrict__ woT,
                           uint32_t* __restrict__ xp) {
    const int z = blockIdx.z;
    int tx = threadIdx.x, ty = threadIdx.y;

    if (z == 4) {
        int bidl = blockIdx.y * 128 + blockIdx.x;
        if (bidl >= 8192) return;
        int idx = bidl * 256 + ty * 32 + tx;
        int s = idx >> 10;
        int d4 = (idx & 1023) << 2;
        float4 v = *(const float4*)&x[(size_t)s * D_MODEL + d4];
        int rowblk = s >> 7, r = s & 127;
        int chunk = d4 >> 6;
        int c2 = (d4 & 63) >> 1;
        __half2 lo = __floats2half2_rn(v.x, v.y);
        __half2 hi = __floats2half2_rn(v.z, v.w);
        uint32_t* dst = &xp[((size_t)rowblk * 64 + chunk) * TILE_U32 + SWZ(r, c2)];
        *(uint2*)dst = make_uint2(*(uint32_t*)&lo, *(uint32_t*)&hi);
        return;
    }

    const float* W; uint32_t* P; int C; int colblk0;
    if (z == 0)      { W = wq; P = wqkv; C = 4096; colblk0 = 0; }
    else if (z == 1) { W = wk; P = wqkv; C = 1024; colblk0 = 32; }
    else if (z == 2) { W = wv; P = wqkv; C = 1024; colblk0 = 40; }
    else             { W = wo; P = woT;  C = 4096; colblk0 = 0; }
    int bx = blockIdx.x * 32;
    if (bx >= C) return;
    int by = blockIdx.y * 32;

    __shared__ float t[32][33];
#pragma unroll
    for (int i = 0; i < 32; i += 8)
        t[ty + i][tx] = W[(size_t)(by + ty + i) * C + bx + tx];
    __syncthreads();
    const int kk2 = tx & 15;
    const int kglob = by + 2 * kk2;
    const int chunk = kglob >> 6;
    const int c2 = (kglob & 63) >> 1;
    const int nbase = (tx >> 4) * 8 + ty;
#pragma unroll
    for (int g = 0; g < 2; g++) {
        int nloc = nbase + g * 16;
        int n = bx + nloc;
        int colblk = colblk0 + (n >> 7), r = n & 127;
        __half2 v = __floats2half2_rn(t[2 * kk2][nloc], t[2 * kk2 + 1][nloc]);
        P[((size_t)colblk * 64 + chunk) * TILE_U32 + SWZ(r, c2)] = *(uint32_t*)&v;
    }
}

// ---------------------------------------------------------------------------
// Tensor-core flash attention (causal), ldmatrix-fed, LPT-ordered.
// 1 CTA = 64 queries x 1 head (4 warps, 2 CTAs/SM). 3-stage pipeline.
// Lazy-rescale softmax (fixed reference M, warp-uniform skip).
// ---------------------------------------------------------------------------
#define FA_STAGE 32768
#define FA_NSTG 3
#define FA_SMEM (1024 + FA_NSTG * FA_STAGE)

__global__ __launch_bounds__(128, 2)
void fa_kernel(const uint32_t* __restrict__ Q, const uint32_t* __restrict__ Kp,
               const uint32_t* __restrict__ Vp, uint32_t* __restrict__ O) {
    extern __shared__ char smem[];
    const uint32_t sb = smem_u32(smem);
    const int tid = threadIdx.x;
    const int w = tid >> 5, lane = tid & 31;
    const int lq = lane >> 3, lr = lane & 7;
    const int h = blockIdx.y;
    const int kvh = h >> 2;
    const int qblk = gridDim.x - 1 - blockIdx.x;    // LPT: longest CTAs first
    const int q0 = qblk * 64;

    if (tid == 0) {
#pragma unroll
        for (int s = 0; s < FA_NSTG; s++) MBARRIER_INIT(sb + 8 * s, 1);
    }
    __syncthreads();

    const int rq = q0 + w * 16 + (lane >> 2);
    const uint32_t* q0p = Q + ((size_t)rq * N_HEADS + h) * 64;
    const uint32_t* q1p = Q + ((size_t)(rq + 8) * N_HEADS + h) * 64;
    uint32_t qf[8][4];
#pragma unroll
    for (int kk = 0; kk < 8; kk++) {
        int cb = kk * 8 + (lane & 3);
        qf[kk][0] = q0p[cb];
        qf[kk][1] = q1p[cb];
        qf[kk][2] = q0p[cb + 4];
        qf[kk][3] = q1p[cb + 4];
    }

    const int nc = qblk + 1;
    const uint32_t* Kt = Kp + (size_t)(kvh * 32) * 4096;
    const uint32_t* Vt = Vp + (size_t)(kvh * 32) * 4096;

    auto issue = [&](int c, int st) {
        uint32_t base = sb + 1024 + st * FA_STAGE;
        MBARRIER_EXPECT_TX(sb + 8 * st, FA_STAGE);
        bulk_g2s(base, Kt + (size_t)c * 4096, 16384, sb + 8 * st);
        bulk_g2s(base + 16384, Vt + (size_t)c * 4096, 16384, sb + 8 * st);
    };
    if (tid == 0) {
        issue(0, 0);
        if (nc > 1) issue(1, 1);
        if (nc > 2) issue(2, 2);
    }

    float M0 = -1e30f, M1 = -1e30f, lp0 = 0.f, lp1 = 0.f;
    float oacc[16][4];
#pragma unroll
    for (int i = 0; i < 16; i++)
#pragma unroll
        for (int j = 0; j < 4; j++) oacc[i][j] = 0.f;

    int fph = 0;
    int st = 0;
    const int sbrow = (lq >> 1) * 8 + lr;
    const int sbc4 = (lq & 1) * 4;

    for (int c = 0; c < nc; c++) {
        MBARRIER_WAIT_PARITY(sb + 8 * st, (fph >> st) & 1);
        fph ^= 1 << st;

        const uint32_t KhA = sb + 1024 + st * FA_STAGE;
        const uint32_t VsA = KhA + 16384;

        float sacc[8][4];
#pragma unroll
        for (int nt = 0; nt < 8; nt++)
#pragma unroll
            for (int j = 0; j < 4; j++) sacc[nt][j] = 0.f;

#pragma unroll
        for (int kk = 0; kk < 8; kk++) {
            const int c2b = kk * 8 + sbc4;
#pragma unroll
            for (int j = 0; j < 4; j++) {
                uint32_t adr = 4 * KSWZ(sbrow + j * 16, c2b);
                uint32_t h0, h1, h2, h3;
                LDSM4(h0, h1, h2, h3, KhA + adr);
                uint32_t bh0[2] = { h0, h1 }, bh1[2] = { h2, h3 };
                mma16816(sacc[2 * j],     qf[kk], bh0);
                mma16816(sacc[2 * j + 1], qf[kk], bh1);
            }
        }

        if (c == qblk) {
#pragma unroll
            for (int nt = 0; nt < 8; nt++) {
                int cg = c * 64 + nt * 8 + 2 * (lane & 3);
                if (cg > rq)          sacc[nt][0] = -1e30f;
                if (cg + 1 > rq)      sacc[nt][1] = -1e30f;
                if (cg > rq + 8)      sacc[nt][2] = -1e30f;
                if (cg + 1 > rq + 8)  sacc[nt][3] = -1e30f;
            }
        }

        float mx0 = -1e30f, mx1 = -1e30f;
#pragma unroll
        for (int nt = 0; nt < 8; nt++) {
            mx0 = fmaxf(mx0, fmaxf(sacc[nt][0], sacc[nt][1]));
            mx1 = fmaxf(mx1, fmaxf(sacc[nt][2], sacc[nt][3]));
        }
        bool trig = (mx0 > M0 + 6.9f) || (mx1 > M1 + 6.9f);
        if (__any_sync(0xffffffff, trig)) {
            float r0 = fmaxf(mx0, __shfl_xor_sync(0xffffffff, mx0, 1));
            r0 = fmaxf(r0, __shfl_xor_sync(0xffffffff, r0, 2));
            float r1 = fmaxf(mx1, __shfl_xor_sync(0xffffffff, mx1, 1));
            r1 = fmaxf(r1, __shfl_xor_sync(0xffffffff, r1, 2));
            float Mn0 = fmaxf(M0, r0), Mn1 = fmaxf(M1, r1);
            float c0 = __expf(M0 - Mn0), c1 = __expf(M1 - Mn1);
            lp0 *= c0; lp1 *= c1;
#pragma unroll
            for (int i = 0; i < 16; i++) {
                oacc[i][0] *= c0; oacc[i][1] *= c0;
                oacc[i][2] *= c1; oacc[i][3] *= c1;
            }
            M0 = Mn0; M1 = Mn1;
        }

        uint32_t pf[4][4];
#pragma unroll
        for (int nt = 0; nt < 8; nt++) {
            float p0 = __expf(sacc[nt][0] - M0);
            float p1 = __expf(sacc[nt][1] - M0);
            float p2 = __expf(sacc[nt][2] - M1);
            float p3 = __expf(sacc[nt][3] - M1);
            lp0 += p0 + p1; lp1 += p2 + p3;
            __half2 h01 = __floats2half2_rn(p0, p1);
            __half2 h23 = __floats2half2_rn(p2, p3);
            int kt = nt >> 1, hi = (nt & 1) << 1;
            pf[kt][hi]     = *(uint32_t*)&h01;
            pf[kt][hi + 1] = *(uint32_t*)&h23;
        }

#pragma unroll
        for (int jj = 0; jj < 8; jj++) {
#pragma unroll
            for (int kt = 0; kt < 4; kt++) {
                uint32_t b0, b1, b2, b3;
                LDSM4(b0, b1, b2, b3,
                      VsA + 4 * VSWZ(sbrow + jj * 16, kt * 8 + sbc4));
                uint32_t blo[2] = { b0, b1 }, bhi[2] = { b2, b3 };
                mma16816(oacc[2 * jj],     pf[kt], blo);
                mma16816(oacc[2 * jj + 1], pf[kt], bhi);
            }
        }

        __syncthreads();
        if (tid == 0 && c + 3 < nc) issue(c + 3, st);

        st++; if (st == FA_NSTG) st = 0;
    }

    float l0 = lp0, l1 = lp1;
    l0 += __shfl_xor_sync(0xffffffff, l0, 1);
    l0 += __shfl_xor_sync(0xffffffff, l0, 2);
    l1 += __shfl_xor_sync(0xffffffff, l1, 1);
    l1 += __shfl_xor_sync(0xffffffff, l1, 2);

    float i0 = 1.f / l0, i1 = 1.f / l1;
    const int s0r = rq, s1r = rq + 8;
    const int rb0 = s0r >> 7, ri0 = s0r & 127;
    const int rb1 = s1r >> 7, ri1 = s1r & 127;
#pragma unroll
    for (int nt2 = 0; nt2 < 16; nt2++) {
        int d = nt2 * 8 + 2 * (lane & 3);
        int gdim = h * HD + d;
        int chunk = gdim >> 6;
        int c2 = (gdim & 63) >> 1;
        __half2 vlo = __floats2half2_rn(oacc[nt2][0] * i0, oacc[nt2][1] * i0);
        __half2 vhi = __floats2half2_rn(oacc[nt2][2] * i1, oacc[nt2][3] * i1);
        O[((size_t)rb0 * 64 + chunk) * TILE_U32 + SWZ(ri0, c2)] = *(uint32_t*)&vlo;
        O[((size_t)rb1 * 64 + chunk) * TILE_U32 + SWZ(ri1, c2)] = *(uint32_t*)&vhi;
    }
}

// ---------------------------------------------------------------------------
// Host launcher
// ---------------------------------------------------------------------------
extern "C" void kernel_launch(void* const* d_in, const int* in_sizes, int n_in,
                              void* d_out, int out_size) {
    const float* x  = (const float*)d_in[0];
    const float* fc = (const float*)d_in[1];
    const float* fs = (const float*)d_in[2];
    const float* wq = (const float*)d_in[4];
    const float* wk = (const float*)d_in[5];
    const float* wv = (const float*)d_in[6];
    const float* wo = (const float*)d_in[7];
    float* out = (float*)d_out;

    uint32_t *qp, *ap, *xp, *wqkv, *woT, *kh, *vt;
    cudaGetSymbolAddress((void**)&qp, g_qh);
    cudaGetSymbolAddress((void**)&ap, g_attn);
    cudaGetSymbolAddress((void**)&xp, g_xp);
    cudaGetSymbolAddress((void**)&wqkv, g_wqkv);
    cudaGetSymbolAddress((void**)&woT, g_woT);
    cudaGetSymbolAddress((void**)&kh, g_kh);
    cudaGetSymbolAddress((void**)&vt, g_vt);

    cudaFuncSetAttribute(mma_gemm, cudaFuncAttributeMaxDynamicSharedMemorySize, GEMM_SMEM);
    cudaFuncSetAttribute(fa_kernel, cudaFuncAttributeMaxDynamicSharedMemorySize, FA_SMEM);

    // 1: all weight packs + x pack in one launch
    pack_w_all<<<dim3(128, 128, 5), dim3(32, 8)>>>(wq, wk, wv, wo, x, wqkv, woT, xp);

    // 2: fused QKV projection + rope + K-pack + V^T packing epilogues
    mma_gemm<<<dim3(48, S_LEN / 128), 256, GEMM_SMEM>>>(
        xp, wqkv, nullptr, S_LEN, 6144, 4096, 1, fc, fs, qp, kh, vt);

    // 3: flash attention (tensor cores, 64-query CTAs, LPT order, 3-stage)
    fa_kernel<<<dim3(S_LEN / 64, N_HEADS), 128, FA_SMEM>>>(qp, kh, vt, ap);

    // 4: output projection
    mma_gemm<<<dim3(4096 / 128, S_LEN / 128), 256, GEMM_SMEM>>>(
        ap, woT, out, S_LEN, 4096, 4096, 0, nullptr, nullptr, nullptr, nullptr, nullptr);
}